// round 2
// baseline (speedup 1.0000x reference)
#include <cuda_runtime.h>
#include <cuda_fp16.h>
#include <cstdint>

// ============================================================================
// y[m,n] = sum_k x[m,k] * ((q[k,n]-zp)*scale) + bias[n]
// Decomposition: W = scale*(q-128) + scale*(128-zp);  (q-128) exact in fp16.
//   acc = half(x) @ half(q-128)   (fp32 accum via mma.sync HMMA)
//   y = scale*acc + scale*(128-zp)*rowsum(x)[m] + bias[n]
// Portable-PTX path only (target sm_103 lacks tcgen05/TMEM/wgmma):
//   cp.async multistage pipeline + ldmatrix + mma.sync.m16n8k16
// ============================================================================

#define M_TOT 4096
#define N_TOT 4096
#define K_TOT 4096

__device__ __align__(256) __half g_A[(size_t)M_TOT * K_TOT]; // x fp16 [M,K]
__device__ __align__(256) __half g_B[(size_t)N_TOT * K_TOT]; // (q-128) fp16 [N,K]
__device__ float g_rowsum[M_TOT];

// ---------------------------------------------------------------------------
__device__ __forceinline__ uint32_t smem_to_u32(const void* p) {
    uint32_t a;
    asm("{ .reg .u64 t; cvta.to.shared.u64 t, %1; cvt.u32.u64 %0, t; }"
        : "=r"(a) : "l"(p));
    return a;
}

#define SWZ(o) ((o) ^ (((o) >> 3) & 0x70))

#define CP_ASYNC_16(dst, src) \
    asm volatile("cp.async.cg.shared.global [%0], [%1], 16;" \
                 :: "r"(dst), "l"(src) : "memory")
#define CP_COMMIT() asm volatile("cp.async.commit_group;" ::: "memory")
#define CP_WAIT(n)  asm volatile("cp.async.wait_group %0;" :: "n"(n) : "memory")

#define LDSM_X4(R0, R1, R2, R3, ADDR) \
    asm volatile("ldmatrix.sync.aligned.m8n8.x4.shared.b16 {%0,%1,%2,%3}, [%4];" \
                 : "=r"(R0), "=r"(R1), "=r"(R2), "=r"(R3) : "r"(ADDR))

#define MMA16816(C, A0, A1, A2, A3, B0, B1) \
    asm volatile("mma.sync.aligned.m16n8k16.row.col.f32.f16.f16.f32 " \
                 "{%0,%1,%2,%3}, {%4,%5,%6,%7}, {%8,%9}, {%0,%1,%2,%3};" \
                 : "+f"((C)[0]), "+f"((C)[1]), "+f"((C)[2]), "+f"((C)[3]) \
                 : "r"(A0), "r"(A1), "r"(A2), "r"(A3), "r"(B0), "r"(B1))

// ---------------------------------------------------------------------------
// Prep 1: x (fp32) -> g_A (fp16) + per-row sums
// ---------------------------------------------------------------------------
__global__ void prep_x_kernel(const float* __restrict__ x) {
    __shared__ float red[256];
    int m = blockIdx.x;
    const float4* xr = reinterpret_cast<const float4*>(x + (size_t)m * K_TOT);
    __half2* ar = reinterpret_cast<__half2*>(g_A + (size_t)m * K_TOT);
    float s = 0.0f;
    for (int i = threadIdx.x; i < K_TOT / 4; i += 256) {
        float4 v = xr[i];
        ar[2 * i]     = __floats2half2_rn(v.x, v.y);
        ar[2 * i + 1] = __floats2half2_rn(v.z, v.w);
        s += (v.x + v.y) + (v.z + v.w);
    }
    red[threadIdx.x] = s;
    __syncthreads();
    for (int o = 128; o > 0; o >>= 1) {
        if (threadIdx.x < o) red[threadIdx.x] += red[threadIdx.x + o];
        __syncthreads();
    }
    if (threadIdx.x == 0) g_rowsum[m] = red[0];
}

// ---------------------------------------------------------------------------
// Prep 2: W int32 [K, N] -> g_B fp16 (q - 128) in [N, K] layout (transpose)
// ---------------------------------------------------------------------------
__global__ void prep_w_kernel(const int* __restrict__ W) {
    __shared__ __half tile[32][33];
    int n0 = blockIdx.x * 32;
    int k0 = blockIdx.y * 32;
    int tx = threadIdx.x, ty = threadIdx.y;  // 32 x 8
    #pragma unroll
    for (int j = 0; j < 32; j += 8) {
        int k = k0 + ty + j;
        int n = n0 + tx;
        tile[ty + j][tx] = __int2half_rn(W[(size_t)k * N_TOT + n] - 128);
    }
    __syncthreads();
    #pragma unroll
    for (int j = 0; j < 32; j += 8) {
        int n = n0 + ty + j;
        int k = k0 + tx;
        g_B[(size_t)n * K_TOT + k] = tile[tx][ty + j];
    }
}

// ---------------------------------------------------------------------------
// GEMM: BM=128, BN=256, BK=64, 4-stage cp.async pipeline, 8 warps.
// Warp grid 2(M) x 4(N); warp tile 64x64; mma.sync m16n8k16 f32 accum.
// ---------------------------------------------------------------------------
static constexpr int BM = 128;
static constexpr int BN = 256;
static constexpr int BK = 64;           // 128 bytes per row
static constexpr int STAGES = 4;
static constexpr int NCHUNK = K_TOT / BK;                // 64
static constexpr int A_BYTES   = BM * 128;               // 16384
static constexpr int B_BYTES   = BN * 128;               // 32768
static constexpr int STG_BYTES = A_BYTES + B_BYTES;      // 49152
static constexpr int DYN_SMEM  = 1024 + STAGES * STG_BYTES;  // 197632
static constexpr int A_JOBS = BM * 8;                    // 1024 x 16B
static constexpr int JOBS   = (BM + BN) * 8;             // 3072 x 16B

__global__ __launch_bounds__(256, 1)
void gemm_kernel(const float* __restrict__ scale_p,
                 const float* __restrict__ zp_p,
                 const float* __restrict__ bias,
                 float* __restrict__ out) {
    extern __shared__ char dyn_smem[];
    const uint32_t base = (smem_to_u32(dyn_smem) + 1023u) & ~1023u;

    const int tid  = threadIdx.x;
    const int lane = tid & 31;
    const int wid  = tid >> 5;
    const int warpM = wid & 1;    // 0..1
    const int warpN = wid >> 1;   // 0..3

    const __half* Abase = g_A + (size_t)(blockIdx.y * BM) * K_TOT;
    const __half* Bbase = g_B + (size_t)(blockIdx.x * BN) * K_TOT;

    // Per-lane ldmatrix address components
    const int rowA = lane & 15;                       // A: rows m0..m0+15
    const int khA  = (lane >> 4) * 8;                 // A: k half select
    const int rowB = (lane & 7) + ((lane & 16) >> 1); // B: n within n16 tile
    const int khB  = ((lane >> 3) & 1) * 8;           // B: k half select

    float acc[4][8][4];
    #pragma unroll
    for (int i = 0; i < 4; i++)
        #pragma unroll
        for (int j = 0; j < 8; j++)
            #pragma unroll
            for (int t = 0; t < 4; t++) acc[i][j][t] = 0.0f;

    // ---- async stage loader ----
    auto load_stage = [&](int c, int st) {
        const int kofs = c * BK;
        const uint32_t sa = base + (uint32_t)st * STG_BYTES;
        const uint32_t sb = sa + A_BYTES;
        #pragma unroll
        for (int j = tid; j < JOBS; j += 256) {
            if (j < A_JOBS) {
                int r = j >> 3, cc = j & 7;
                uint32_t dst = sa + SWZ((uint32_t)(r * 128 + cc * 16));
                CP_ASYNC_16(dst, Abase + (size_t)r * K_TOT + kofs + cc * 8);
            } else {
                int jj = j - A_JOBS;
                int r = jj >> 3, cc = jj & 7;
                uint32_t dst = sb + SWZ((uint32_t)(r * 128 + cc * 16));
                CP_ASYNC_16(dst, Bbase + (size_t)r * K_TOT + kofs + cc * 8);
            }
        }
    };

    // ---- prologue: fill STAGES-1 stages ----
    #pragma unroll
    for (int s = 0; s < STAGES - 1; s++) {
        load_stage(s, s);
        CP_COMMIT();
    }

    // ---- mainloop ----
    for (int c = 0; c < NCHUNK; c++) {
        CP_WAIT(STAGES - 2);
        __syncthreads();

        const int st = c & (STAGES - 1);
        if (c + STAGES - 1 < NCHUNK) load_stage(c + STAGES - 1, (c + STAGES - 1) & (STAGES - 1));
        CP_COMMIT();

        const uint32_t sa = base + (uint32_t)st * STG_BYTES;
        const uint32_t sb = sa + A_BYTES;

        #pragma unroll
        for (int ks = 0; ks < 4; ks++) {
            // B fragments for the whole 64-wide warp N-tile (4 x n16)
            uint32_t b[4][4];
            #pragma unroll
            for (int q = 0; q < 4; q++) {
                uint32_t off = (uint32_t)((warpN * 64 + q * 16 + rowB) * 128 +
                                          (ks * 16 + khB) * 2);
                LDSM_X4(b[q][0], b[q][1], b[q][2], b[q][3], sb + SWZ(off));
            }
            #pragma unroll
            for (int mt = 0; mt < 4; mt++) {
                uint32_t a0, a1, a2, a3;
                uint32_t off = (uint32_t)((warpM * 64 + mt * 16 + rowA) * 128 +
                                          (ks * 16 + khA) * 2);
                LDSM_X4(a0, a1, a2, a3, sa + SWZ(off));
                #pragma unroll
                for (int q = 0; q < 4; q++) {
                    MMA16816(acc[mt][2 * q],     a0, a1, a2, a3, b[q][0], b[q][1]);
                    MMA16816(acc[mt][2 * q + 1], a0, a1, a2, a3, b[q][2], b[q][3]);
                }
            }
        }
        __syncthreads();
    }

    // ---- epilogue ----
    const float scale = scale_p[0];
    const float zp    = zp_p[0];
    const float kz    = scale * (128.0f - zp);
    const int mBase = blockIdx.y * BM + warpM * 64;
    const int nBase = blockIdx.x * BN + warpN * 64;

    #pragma unroll
    for (int mt = 0; mt < 4; mt++) {
        const int r0 = mBase + mt * 16 + (lane >> 2);
        const int r1 = r0 + 8;
        const float ct0 = kz * g_rowsum[r0];
        const float ct1 = kz * g_rowsum[r1];
        float* o0 = out + (size_t)r0 * N_TOT;
        float* o1 = out + (size_t)r1 * N_TOT;
        #pragma unroll
        for (int nt = 0; nt < 8; nt++) {
            const int col = nBase + nt * 8 + 2 * (lane & 3);
            const float2 bv = *reinterpret_cast<const float2*>(bias + col);
            float2 v0, v1;
            v0.x = fmaf(scale, acc[mt][nt][0], ct0 + bv.x);
            v0.y = fmaf(scale, acc[mt][nt][1], ct0 + bv.y);
            v1.x = fmaf(scale, acc[mt][nt][2], ct1 + bv.x);
            v1.y = fmaf(scale, acc[mt][nt][3], ct1 + bv.y);
            *reinterpret_cast<float2*>(o0 + col) = v0;
            *reinterpret_cast<float2*>(o1 + col) = v1;
        }
    }
}

// ---------------------------------------------------------------------------
extern "C" void kernel_launch(void* const* d_in, const int* in_sizes, int n_in,
                              void* d_out, int out_size) {
    const float* x     = (const float*)d_in[0];
    const int*   q     = (const int*)d_in[1];
    const float* scale = (const float*)d_in[2];
    const float* zp    = (const float*)d_in[3];
    const float* bias  = (const float*)d_in[4];
    float* out = (float*)d_out;

    cudaFuncSetAttribute(gemm_kernel,
                         cudaFuncAttributeMaxDynamicSharedMemorySize, DYN_SMEM);

    prep_x_kernel<<<M_TOT, 256>>>(x);
    prep_w_kernel<<<dim3(N_TOT / 32, K_TOT / 32), dim3(32, 8)>>>(q);
    gemm_kernel<<<dim3(N_TOT / BN, M_TOT / BM), 256, DYN_SMEM>>>(
        scale, zp, bias, out);
}

// round 3
// speedup vs baseline: 1.0216x; 1.0216x over previous
#include <cuda_runtime.h>
#include <cuda_fp16.h>
#include <cstdint>

// ============================================================================
// y[m,n] = sum_k x[m,k] * ((q[k,n]-zp)*scale) + bias[n]
// Decomposition: W = scale*(q-128) + scale*(128-zp);  (q-128) exact in fp16.
//   acc = half(x) @ half(q-128)   (fp32 accum via mma.sync HMMA)
//   y = scale*acc + scale*(128-zp)*rowsum(x)[m] + bias[n]
// Portable-PTX path (target sm_103 lacks tcgen05/TMEM/wgmma):
//   cp.async multistage pipeline + ldmatrix + mma.sync.m16n8k16
// ============================================================================

#define M_TOT 4096
#define N_TOT 4096
#define K_TOT 4096

__device__ __align__(256) __half g_A[(size_t)M_TOT * K_TOT]; // x fp16 [M,K]
__device__ __align__(256) __half g_B[(size_t)N_TOT * K_TOT]; // (q-128) fp16 [N,K]
__device__ float g_rowsum[M_TOT];

// ---------------------------------------------------------------------------
__device__ __forceinline__ uint32_t smem_to_u32(const void* p) {
    uint32_t a;
    asm("{ .reg .u64 t; cvta.to.shared.u64 t, %1; cvt.u32.u64 %0, t; }"
        : "=r"(a) : "l"(p));
    return a;
}

#define SWZ(o) ((o) ^ (((o) >> 3) & 0x70))

#define CP_ASYNC_16(dst, src) \
    asm volatile("cp.async.cg.shared.global [%0], [%1], 16;" \
                 :: "r"(dst), "l"(src) : "memory")
#define CP_COMMIT() asm volatile("cp.async.commit_group;" ::: "memory")
#define CP_WAIT(n)  asm volatile("cp.async.wait_group %0;" :: "n"(n) : "memory")

#define LDSM_X4(R0, R1, R2, R3, ADDR) \
    asm volatile("ldmatrix.sync.aligned.m8n8.x4.shared.b16 {%0,%1,%2,%3}, [%4];" \
                 : "=r"(R0), "=r"(R1), "=r"(R2), "=r"(R3) : "r"(ADDR))

#define MMA16816(C, A0, A1, A2, A3, B0, B1) \
    asm volatile("mma.sync.aligned.m16n8k16.row.col.f32.f16.f16.f32 " \
                 "{%0,%1,%2,%3}, {%4,%5,%6,%7}, {%8,%9}, {%0,%1,%2,%3};" \
                 : "+f"((C)[0]), "+f"((C)[1]), "+f"((C)[2]), "+f"((C)[3]) \
                 : "r"(A0), "r"(A1), "r"(A2), "r"(A3), "r"(B0), "r"(B1))

// ---------------------------------------------------------------------------
// Merged prep: blocks [0,4096) convert x rows + rowsum; blocks [4096, 20480)
// transpose+convert 32x32 tiles of W.
// ---------------------------------------------------------------------------
__global__ void prep_kernel(const float* __restrict__ x,
                            const int* __restrict__ W) {
    __shared__ float red[256];
    __shared__ __half tile[32][33];
    const int tid = threadIdx.x;

    if (blockIdx.x < M_TOT) {
        // ---- x -> fp16 + rowsum ----
        const int m = blockIdx.x;
        const float4* xr = reinterpret_cast<const float4*>(x + (size_t)m * K_TOT);
        __half2* ar = reinterpret_cast<__half2*>(g_A + (size_t)m * K_TOT);
        float s = 0.0f;
        for (int i = tid; i < K_TOT / 4; i += 256) {
            float4 v = xr[i];
            ar[2 * i]     = __floats2half2_rn(v.x, v.y);
            ar[2 * i + 1] = __floats2half2_rn(v.z, v.w);
            s += (v.x + v.y) + (v.z + v.w);
        }
        red[tid] = s;
        __syncthreads();
        for (int o = 128; o > 0; o >>= 1) {
            if (tid < o) red[tid] += red[tid + o];
            __syncthreads();
        }
        if (tid == 0) g_rowsum[m] = red[0];
    } else {
        // ---- W int32 [K,N] -> fp16 (q-128) in [N,K] ----
        const int t  = blockIdx.x - M_TOT;
        const int n0 = (t & (N_TOT / 32 - 1)) * 32;
        const int k0 = (t >> 7) * 32;
        const int tx = tid & 31, ty = tid >> 5;  // 32 x 8
        #pragma unroll
        for (int j = 0; j < 32; j += 8) {
            int k = k0 + ty + j;
            int n = n0 + tx;
            tile[ty + j][tx] = __int2half_rn(W[(size_t)k * N_TOT + n] - 128);
        }
        __syncthreads();
        #pragma unroll
        for (int j = 0; j < 32; j += 8) {
            int n = n0 + ty + j;
            int k = k0 + tx;
            g_B[(size_t)n * K_TOT + k] = tile[tx][ty + j];
        }
    }
}

// ---------------------------------------------------------------------------
// GEMM: BM=128, BN=256, BK=64, 4-stage cp.async pipeline, 8 warps.
// Warp grid 2(M) x 4(N); warp tile 64x64; mma.sync m16n8k16 f32 accum.
// B fragments double-buffered across ks steps.
// ---------------------------------------------------------------------------
static constexpr int BM = 128;
static constexpr int BN = 256;
static constexpr int BK = 64;           // 128 bytes per row
static constexpr int STAGES = 4;
static constexpr int NCHUNK = K_TOT / BK;                // 64
static constexpr int A_BYTES   = BM * 128;               // 16384
static constexpr int B_BYTES   = BN * 128;               // 32768
static constexpr int STG_BYTES = A_BYTES + B_BYTES;      // 49152
static constexpr int DYN_SMEM  = 1024 + STAGES * STG_BYTES;  // 197632
static constexpr int A_JOBS = BM * 8;                    // 1024 x 16B
static constexpr int JOBS   = (BM + BN) * 8;             // 3072 x 16B

__global__ __launch_bounds__(256, 1)
void gemm_kernel(const float* __restrict__ scale_p,
                 const float* __restrict__ zp_p,
                 const float* __restrict__ bias,
                 float* __restrict__ out) {
    extern __shared__ char dyn_smem[];
    const uint32_t base = (smem_to_u32(dyn_smem) + 1023u) & ~1023u;

    const int tid  = threadIdx.x;
    const int lane = tid & 31;
    const int wid  = tid >> 5;
    const int warpM = wid & 1;    // 0..1
    const int warpN = wid >> 1;   // 0..3

    const __half* Abase = g_A + (size_t)(blockIdx.y * BM) * K_TOT;
    const __half* Bbase = g_B + (size_t)(blockIdx.x * BN) * K_TOT;

    // Per-lane ldmatrix address components
    const int rowA = lane & 15;                       // A: rows m0..m0+15
    const int khA  = (lane >> 4) * 8;                 // A: k half select
    const int rowB = (lane & 7) + ((lane & 16) >> 1); // B: n within n16 tile
    const int khB  = ((lane >> 3) & 1) * 8;           // B: k half select

    float acc[4][8][4];
    #pragma unroll
    for (int i = 0; i < 4; i++)
        #pragma unroll
        for (int j = 0; j < 8; j++)
            #pragma unroll
            for (int t = 0; t < 4; t++) acc[i][j][t] = 0.0f;

    // ---- async stage loader ----
    auto load_stage = [&](int c, int st) {
        const int kofs = c * BK;
        const uint32_t sa = base + (uint32_t)st * STG_BYTES;
        const uint32_t sb = sa + A_BYTES;
        #pragma unroll
        for (int j = tid; j < JOBS; j += 256) {
            if (j < A_JOBS) {
                int r = j >> 3, cc = j & 7;
                uint32_t dst = sa + SWZ((uint32_t)(r * 128 + cc * 16));
                CP_ASYNC_16(dst, Abase + (size_t)r * K_TOT + kofs + cc * 8);
            } else {
                int jj = j - A_JOBS;
                int r = jj >> 3, cc = jj & 7;
                uint32_t dst = sb + SWZ((uint32_t)(r * 128 + cc * 16));
                CP_ASYNC_16(dst, Bbase + (size_t)r * K_TOT + kofs + cc * 8);
            }
        }
    };

    // ---- prologue: fill STAGES-1 stages ----
    #pragma unroll
    for (int s = 0; s < STAGES - 1; s++) {
        load_stage(s, s);
        CP_COMMIT();
    }

    // ---- mainloop ----
    for (int c = 0; c < NCHUNK; c++) {
        CP_WAIT(STAGES - 2);
        __syncthreads();   // all warps done reading stage (c-1)&3; stage c&3 ready

        const int st = c & (STAGES - 1);
        if (c + STAGES - 1 < NCHUNK)
            load_stage(c + STAGES - 1, (c + STAGES - 1) & (STAGES - 1));
        CP_COMMIT();

        const uint32_t sa = base + (uint32_t)st * STG_BYTES;
        const uint32_t sb = sa + A_BYTES;

        // B fragments, double-buffered across ks
        uint32_t bf[2][4][4];
        #pragma unroll
        for (int q = 0; q < 4; q++) {
            uint32_t off = (uint32_t)((warpN * 64 + q * 16 + rowB) * 128 + khB * 2);
            LDSM_X4(bf[0][q][0], bf[0][q][1], bf[0][q][2], bf[0][q][3], sb + SWZ(off));
        }

        #pragma unroll
        for (int ks = 0; ks < 4; ks++) {
            const int cur = ks & 1;
            if (ks < 3) {
                const int nxt = cur ^ 1;
                #pragma unroll
                for (int q = 0; q < 4; q++) {
                    uint32_t off = (uint32_t)((warpN * 64 + q * 16 + rowB) * 128 +
                                              ((ks + 1) * 16 + khB) * 2);
                    LDSM_X4(bf[nxt][q][0], bf[nxt][q][1], bf[nxt][q][2], bf[nxt][q][3],
                            sb + SWZ(off));
                }
            }
            #pragma unroll
            for (int mt = 0; mt < 4; mt++) {
                uint32_t a0, a1, a2, a3;
                uint32_t off = (uint32_t)((warpM * 64 + mt * 16 + rowA) * 128 +
                                          (ks * 16 + khA) * 2);
                LDSM_X4(a0, a1, a2, a3, sa + SWZ(off));
                #pragma unroll
                for (int q = 0; q < 4; q++) {
                    MMA16816(acc[mt][2 * q],     a0, a1, a2, a3, bf[cur][q][0], bf[cur][q][1]);
                    MMA16816(acc[mt][2 * q + 1], a0, a1, a2, a3, bf[cur][q][2], bf[cur][q][3]);
                }
            }
        }
        // no trailing __syncthreads: next iteration's wait+sync protects reuse
    }

    // ---- epilogue ----
    const float scale = scale_p[0];
    const float zp    = zp_p[0];
    const float kz    = scale * (128.0f - zp);
    const int mBase = blockIdx.y * BM + warpM * 64;
    const int nBase = blockIdx.x * BN + warpN * 64;

    #pragma unroll
    for (int mt = 0; mt < 4; mt++) {
        const int r0 = mBase + mt * 16 + (lane >> 2);
        const int r1 = r0 + 8;
        const float ct0 = kz * g_rowsum[r0];
        const float ct1 = kz * g_rowsum[r1];
        float* o0 = out + (size_t)r0 * N_TOT;
        float* o1 = out + (size_t)r1 * N_TOT;
        #pragma unroll
        for (int nt = 0; nt < 8; nt++) {
            const int col = nBase + nt * 8 + 2 * (lane & 3);
            const float2 bv = *reinterpret_cast<const float2*>(bias + col);
            float2 v0, v1;
            v0.x = fmaf(scale, acc[mt][nt][0], ct0 + bv.x);
            v0.y = fmaf(scale, acc[mt][nt][1], ct0 + bv.y);
            v1.x = fmaf(scale, acc[mt][nt][2], ct1 + bv.x);
            v1.y = fmaf(scale, acc[mt][nt][3], ct1 + bv.y);
            *reinterpret_cast<float2*>(o0 + col) = v0;
            *reinterpret_cast<float2*>(o1 + col) = v1;
        }
    }
}

// ---------------------------------------------------------------------------
extern "C" void kernel_launch(void* const* d_in, const int* in_sizes, int n_in,
                              void* d_out, int out_size) {
    const float* x     = (const float*)d_in[0];
    const int*   q     = (const int*)d_in[1];
    const float* scale = (const float*)d_in[2];
    const float* zp    = (const float*)d_in[3];
    const float* bias  = (const float*)d_in[4];
    float* out = (float*)d_out;

    cudaFuncSetAttribute(gemm_kernel,
                         cudaFuncAttributeMaxDynamicSharedMemorySize, DYN_SMEM);

    prep_kernel<<<M_TOT + (K_TOT / 32) * (N_TOT / 32), 256>>>(x, q);
    gemm_kernel<<<dim3(N_TOT / BN, M_TOT / BM), 256, DYN_SMEM>>>(
        scale, zp, bias, out);
}

// round 4
// speedup vs baseline: 1.1472x; 1.1229x over previous
#include <cuda_runtime.h>
#include <cuda_fp16.h>
#include <cstdint>

// ============================================================================
// y[m,n] = sum_k x[m,k] * ((q[k,n]-zp)*scale) + bias[n]
// Decomposition: W = scale*(q-128) + scale*(128-zp);  (q-128) exact in fp16.
//   acc = half(x) @ half(q-128)   (fp32 accum via mma.sync HMMA)
//   y = scale*acc + scale*(128-zp)*rowsum(x)[m] + bias[n]
// R4: occupancy-2 GEMM (BM=128,BN=128,3 stages,128 regs) to close the
//     tensor-pipe gap seen at occ=12.5% / tensor=63%.
// ============================================================================

#define M_TOT 4096
#define N_TOT 4096
#define K_TOT 4096

__device__ __align__(256) __half g_A[(size_t)M_TOT * K_TOT]; // x fp16 [M,K]
__device__ __align__(256) __half g_B[(size_t)N_TOT * K_TOT]; // (q-128) fp16 [N,K]
__device__ float g_rowsum[M_TOT];

// ---------------------------------------------------------------------------
__device__ __forceinline__ uint32_t smem_to_u32(const void* p) {
    uint32_t a;
    asm("{ .reg .u64 t; cvta.to.shared.u64 t, %1; cvt.u32.u64 %0, t; }"
        : "=r"(a) : "l"(p));
    return a;
}

#define SWZ(o) ((o) ^ (((o) >> 3) & 0x70))

#define CP_ASYNC_16(dst, src) \
    asm volatile("cp.async.cg.shared.global [%0], [%1], 16;" \
                 :: "r"(dst), "l"(src) : "memory")
#define CP_COMMIT() asm volatile("cp.async.commit_group;" ::: "memory")
#define CP_WAIT(n)  asm volatile("cp.async.wait_group %0;" :: "n"(n) : "memory")

#define LDSM_X4(R0, R1, R2, R3, ADDR) \
    asm volatile("ldmatrix.sync.aligned.m8n8.x4.shared.b16 {%0,%1,%2,%3}, [%4];" \
                 : "=r"(R0), "=r"(R1), "=r"(R2), "=r"(R3) : "r"(ADDR))

#define MMA16816(C, A0, A1, A2, A3, B0, B1) \
    asm volatile("mma.sync.aligned.m16n8k16.row.col.f32.f16.f16.f32 " \
                 "{%0,%1,%2,%3}, {%4,%5,%6,%7}, {%8,%9}, {%0,%1,%2,%3};" \
                 : "+f"((C)[0]), "+f"((C)[1]), "+f"((C)[2]), "+f"((C)[3]) \
                 : "r"(A0), "r"(A1), "r"(A2), "r"(A3), "r"(B0), "r"(B1))

// ---------------------------------------------------------------------------
// Merged prep: blocks [0,4096) convert x rows + rowsum; blocks [4096, 20480)
// transpose+convert 32x32 tiles of W.
// ---------------------------------------------------------------------------
__global__ void prep_kernel(const float* __restrict__ x,
                            const int* __restrict__ W) {
    __shared__ float red[256];
    __shared__ __half tile[32][33];
    const int tid = threadIdx.x;

    if (blockIdx.x < M_TOT) {
        const int m = blockIdx.x;
        const float4* xr = reinterpret_cast<const float4*>(x + (size_t)m * K_TOT);
        __half2* ar = reinterpret_cast<__half2*>(g_A + (size_t)m * K_TOT);
        float s = 0.0f;
        for (int i = tid; i < K_TOT / 4; i += 256) {
            float4 v = xr[i];
            ar[2 * i]     = __floats2half2_rn(v.x, v.y);
            ar[2 * i + 1] = __floats2half2_rn(v.z, v.w);
            s += (v.x + v.y) + (v.z + v.w);
        }
        red[tid] = s;
        __syncthreads();
        for (int o = 128; o > 0; o >>= 1) {
            if (tid < o) red[tid] += red[tid + o];
            __syncthreads();
        }
        if (tid == 0) g_rowsum[m] = red[0];
    } else {
        const int t  = blockIdx.x - M_TOT;
        const int n0 = (t & (N_TOT / 32 - 1)) * 32;
        const int k0 = (t >> 7) * 32;
        const int tx = tid & 31, ty = tid >> 5;  // 32 x 8
        #pragma unroll
        for (int j = 0; j < 32; j += 8) {
            int k = k0 + ty + j;
            int n = n0 + tx;
            tile[ty + j][tx] = __int2half_rn(W[(size_t)k * N_TOT + n] - 128);
        }
        __syncthreads();
        #pragma unroll
        for (int j = 0; j < 32; j += 8) {
            int n = n0 + ty + j;
            int k = k0 + tx;
            g_B[(size_t)n * K_TOT + k] = tile[tx][ty + j];
        }
    }
}

// ---------------------------------------------------------------------------
// GEMM: BM=128, BN=128, BK=64, 3-stage cp.async pipeline, 8 warps, 2 CTAs/SM.
// Warp grid 2(M) x 4(N); warp tile 64x32; mma.sync m16n8k16 f32 accum.
// ---------------------------------------------------------------------------
static constexpr int BM = 128;
static constexpr int BN = 128;
static constexpr int BK = 64;           // 128 bytes per row
static constexpr int STAGES = 3;
static constexpr int NCHUNK = K_TOT / BK;                // 64
static constexpr int A_BYTES   = BM * 128;               // 16384
static constexpr int B_BYTES   = BN * 128;               // 16384
static constexpr int STG_BYTES = A_BYTES + B_BYTES;      // 32768
static constexpr int DYN_SMEM  = 1024 + STAGES * STG_BYTES;  // 99328
static constexpr int A_JOBS = BM * 8;                    // 1024 x 16B
static constexpr int JOBS   = (BM + BN) * 8;             // 2048 x 16B

__global__ __launch_bounds__(256, 2)
void gemm_kernel(const float* __restrict__ scale_p,
                 const float* __restrict__ zp_p,
                 const float* __restrict__ bias,
                 float* __restrict__ out) {
    extern __shared__ char dyn_smem[];
    const uint32_t base = (smem_to_u32(dyn_smem) + 1023u) & ~1023u;

    const int tid  = threadIdx.x;
    const int lane = tid & 31;
    const int wid  = tid >> 5;
    const int warpM = wid & 1;    // 0..1 (64 rows each)
    const int warpN = wid >> 1;   // 0..3 (32 cols each)

    const __half* Abase = g_A + (size_t)(blockIdx.y * BM) * K_TOT;
    const __half* Bbase = g_B + (size_t)(blockIdx.x * BN) * K_TOT;

    const int rowA = lane & 15;                       // A rows within m16
    const int khA  = (lane >> 4) * 8;                 // A k-half
    const int rowB = (lane & 7) + ((lane & 16) >> 1); // B n within n16
    const int khB  = ((lane >> 3) & 1) * 8;           // B k-half

    float acc[4][4][4];  // [mt 4 x m16][nt 4 x n8][frag]
    #pragma unroll
    for (int i = 0; i < 4; i++)
        #pragma unroll
        for (int j = 0; j < 4; j++)
            #pragma unroll
            for (int t = 0; t < 4; t++) acc[i][j][t] = 0.0f;

    auto load_stage = [&](int c, int st) {
        const int kofs = c * BK;
        const uint32_t sa = base + (uint32_t)st * STG_BYTES;
        const uint32_t sb = sa + A_BYTES;
        #pragma unroll
        for (int j = tid; j < JOBS; j += 256) {
            if (j < A_JOBS) {
                int r = j >> 3, cc = j & 7;
                uint32_t dst = sa + SWZ((uint32_t)(r * 128 + cc * 16));
                CP_ASYNC_16(dst, Abase + (size_t)r * K_TOT + kofs + cc * 8);
            } else {
                int jj = j - A_JOBS;
                int r = jj >> 3, cc = jj & 7;
                uint32_t dst = sb + SWZ((uint32_t)(r * 128 + cc * 16));
                CP_ASYNC_16(dst, Bbase + (size_t)r * K_TOT + kofs + cc * 8);
            }
        }
    };

    // prologue: fill STAGES-1 stages
    #pragma unroll
    for (int s = 0; s < STAGES - 1; s++) {
        load_stage(s, s);
        CP_COMMIT();
    }

    int st = 0;
    for (int c = 0; c < NCHUNK; c++) {
        CP_WAIT(STAGES - 2);
        __syncthreads();

        const int pst = (st + STAGES - 1 == STAGES) ? 0 : st + STAGES - 1 -
                        ((st + STAGES - 1 >= STAGES) ? STAGES : 0);
        if (c + STAGES - 1 < NCHUNK) load_stage(c + STAGES - 1, pst);
        CP_COMMIT();

        const uint32_t sa = base + (uint32_t)st * STG_BYTES;
        const uint32_t sb = sa + A_BYTES;

        #pragma unroll
        for (int ks = 0; ks < 4; ks++) {
            // B fragments: 2 x n16 tiles for this warp's 32-col slice
            uint32_t b[2][4];
            #pragma unroll
            for (int q = 0; q < 2; q++) {
                uint32_t off = (uint32_t)((warpN * 32 + q * 16 + rowB) * 128 +
                                          (ks * 16 + khB) * 2);
                LDSM_X4(b[q][0], b[q][1], b[q][2], b[q][3], sb + SWZ(off));
            }
            #pragma unroll
            for (int mt = 0; mt < 4; mt++) {
                uint32_t a0, a1, a2, a3;
                uint32_t off = (uint32_t)((warpM * 64 + mt * 16 + rowA) * 128 +
                                          (ks * 16 + khA) * 2);
                LDSM_X4(a0, a1, a2, a3, sa + SWZ(off));
                #pragma unroll
                for (int q = 0; q < 2; q++) {
                    MMA16816(acc[mt][2 * q],     a0, a1, a2, a3, b[q][0], b[q][1]);
                    MMA16816(acc[mt][2 * q + 1], a0, a1, a2, a3, b[q][2], b[q][3]);
                }
            }
        }
        st = (st + 1 == STAGES) ? 0 : st + 1;
        // next iteration's wait+sync protects stage reuse
    }

    // ---- epilogue ----
    const float scale = scale_p[0];
    const float zp    = zp_p[0];
    const float kz    = scale * (128.0f - zp);
    const int mBase = blockIdx.y * BM + warpM * 64;
    const int nBase = blockIdx.x * BN + warpN * 32;

    #pragma unroll
    for (int mt = 0; mt < 4; mt++) {
        const int r0 = mBase + mt * 16 + (lane >> 2);
        const int r1 = r0 + 8;
        const float ct0 = kz * g_rowsum[r0];
        const float ct1 = kz * g_rowsum[r1];
        float* o0 = out + (size_t)r0 * N_TOT;
        float* o1 = out + (size_t)r1 * N_TOT;
        #pragma unroll
        for (int nt = 0; nt < 4; nt++) {
            const int col = nBase + nt * 8 + 2 * (lane & 3);
            const float2 bv = *reinterpret_cast<const float2*>(bias + col);
            float2 v0, v1;
            v0.x = fmaf(scale, acc[mt][nt][0], ct0 + bv.x);
            v0.y = fmaf(scale, acc[mt][nt][1], ct0 + bv.y);
            v1.x = fmaf(scale, acc[mt][nt][2], ct1 + bv.x);
            v1.y = fmaf(scale, acc[mt][nt][3], ct1 + bv.y);
            *reinterpret_cast<float2*>(o0 + col) = v0;
            *reinterpret_cast<float2*>(o1 + col) = v1;
        }
    }
}

// ---------------------------------------------------------------------------
extern "C" void kernel_launch(void* const* d_in, const int* in_sizes, int n_in,
                              void* d_out, int out_size) {
    const float* x     = (const float*)d_in[0];
    const int*   q     = (const int*)d_in[1];
    const float* scale = (const float*)d_in[2];
    const float* zp    = (const float*)d_in[3];
    const float* bias  = (const float*)d_in[4];
    float* out = (float*)d_out;

    cudaFuncSetAttribute(gemm_kernel,
                         cudaFuncAttributeMaxDynamicSharedMemorySize, DYN_SMEM);

    prep_kernel<<<M_TOT + (K_TOT / 32) * (N_TOT / 32), 256>>>(x, q);
    gemm_kernel<<<dim3(N_TOT / BN, M_TOT / BM), 256, DYN_SMEM>>>(
        scale, zp, bias, out);
}